// round 17
// baseline (speedup 1.0000x reference)
#include <cuda_runtime.h>
#include <cuda_fp16.h>
#include <math.h>
#include <stdint.h>

#define BATCH 16
#define HDIM  768
#define NDIM  2048
#define KC    64            // k elements per chunk (fp16)
#define PITCH 72            // smem row pitch in halfs (144B, LDSM/cp.async conflict-free)
#define NSTAGE  3
#define NTHREADS 256
#define NWARPS  8
#define NCTAS   296         // persistent grid: fully resident at 2 CTAs/SM

// gemm1: A=Qt 128 rows, B=Kt 128 rows
#define STAGE_A1 (128 * PITCH)
#define STAGE1   (STAGE_A1 + 128 * PITCH)    // 18432 halfs
#define MBAR_OFF1 (NSTAGE * STAGE1 * 2 + 2048)
#define SMEM1     (MBAR_OFF1 + 64)
// gemm2: A=Vh 96 rows, B=Eh 128 rows
#define STAGE_A2 (96 * PITCH)
#define STAGE2   (STAGE_A2 + 128 * PITCH)    // 16128 halfs
#define MBAR_OFF2 (NSTAGE * STAGE2 * 2 + 2048)
#define SMEM2     (MBAR_OFF2 + 64)

// Scratch (allocation-free rule: __device__ globals)
__device__ __half g_Qt[(size_t)BATCH * NDIM * HDIM];  // [b][n][h]
__device__ __half g_Kt[(size_t)BATCH * NDIM * HDIM];  // [b][m][h] = fp16(K+PE)
__device__ __half g_Vh[(size_t)BATCH * HDIM * NDIM];  // [b][h][m]
__device__ __half g_Eh[(size_t)BATCH * NDIM * NDIM];  // [b][n][m] exp(logits)
__device__ float  g_Lpart[(size_t)BATCH * 16 * NDIM];
__device__ float  g_L[(size_t)BATCH * NDIM];          // 1 / rowsum

__device__ __forceinline__ uint32_t smem_u32(const void* p) {
    uint32_t a;
    asm("{ .reg .u64 t; cvta.to.shared.u64 t, %1; cvt.u32.u64 %0, t; }" : "=r"(a) : "l"(p));
    return a;
}
__device__ __forceinline__ void cpa16(uint32_t dst, const void* src) {
    asm volatile("cp.async.cg.shared.global [%0], [%1], 16;" :: "r"(dst), "l"(src));
}

// ---- mbarrier ring machinery ----
#define MBAR_INIT(a, n) \
    asm volatile("mbarrier.init.shared.b64 [%0], %1;" :: "r"(a), "r"((unsigned)(n)) : "memory")
#define MBAR_ARRIVE(a) \
    asm volatile("{\n\t.reg .b64 t;\n\tmbarrier.arrive.shared.b64 t, [%0];\n\t}" \
                 :: "r"(a) : "memory")
#define CP_MBAR_ARRIVE(a) \
    asm volatile("cp.async.mbarrier.arrive.noinc.shared.b64 [%0];" :: "r"(a) : "memory")
#define MBAR_WAIT(a, p) \
    asm volatile("{\n\t.reg .pred P;\n\tLAB%=:\n\t" \
                 "mbarrier.try_wait.parity.acquire.cta.shared::cta.b64 P, [%0], %1, 0x989680;\n\t" \
                 "@!P bra LAB%=;\n\t}" :: "r"(a), "r"((unsigned)(p)) : "memory")

#define LDSM_X4(r0, r1, r2, r3, addr) \
    asm volatile("ldmatrix.sync.aligned.m8n8.x4.shared.b16 {%0,%1,%2,%3}, [%4];" \
                 : "=r"(r0), "=r"(r1), "=r"(r2), "=r"(r3) : "r"(addr))

__device__ __forceinline__ void mma_f16(float* c, const uint32_t* a, const uint32_t* b) {
    asm volatile(
        "mma.sync.aligned.m16n8k16.row.col.f32.f16.f16.f32 "
        "{%0,%1,%2,%3}, {%4,%5,%6,%7}, {%8,%9}, {%0,%1,%2,%3};\n"
        : "+f"(c[0]), "+f"(c[1]), "+f"(c[2]), "+f"(c[3])
        : "r"(a[0]), "r"(a[1]), "r"(a[2]), "r"(a[3]), "r"(b[0]), "r"(b[1]));
}

// ===========================================================================
// Pre-pass 1: transpose+convert, 64x64 tiles.
// ===========================================================================
__global__ __launch_bounds__(512)
void prep_qk(const float* __restrict__ Q, const float* __restrict__ K,
             const float* __restrict__ PE) {
    __shared__ float t[64][65];
    const int b = blockIdx.z, h0 = blockIdx.y * 64, n0 = blockIdx.x * 64;
    const int tid = threadIdx.x;
    const size_t ibase = (size_t)b * HDIM * NDIM;
    const size_t obase = (size_t)b * NDIM * HDIM;

    const int sn = tid >> 3, shb = (tid & 7) * 8;

#pragma unroll
    for (int i = 0; i < 2; i++) {
        const int idx = i * 512 + tid, row = idx >> 4, c4 = (idx & 15) * 4;
        const float4 v = *(const float4*)(Q + ibase + (size_t)(h0 + row) * NDIM + n0 + c4);
        t[row][c4] = v.x; t[row][c4 + 1] = v.y; t[row][c4 + 2] = v.z; t[row][c4 + 3] = v.w;
    }
    __syncthreads();
    {
        __align__(16) __half2 o[4];
#pragma unroll
        for (int j = 0; j < 4; j++)
            o[j] = __floats2half2_rn(t[shb + 2 * j][sn], t[shb + 2 * j + 1][sn]);
        *(uint4*)(g_Qt + obase + (size_t)(n0 + sn) * HDIM + h0 + shb) = *(uint4*)o;
    }
    __syncthreads();

#pragma unroll
    for (int i = 0; i < 2; i++) {
        const int idx = i * 512 + tid, row = idx >> 4, c4 = (idx & 15) * 4;
        const size_t g = ibase + (size_t)(h0 + row) * NDIM + n0 + c4;
        const float4 kv = *(const float4*)(K + g);
        const float4 pv = *(const float4*)(PE + g);
        t[row][c4]     = kv.x + pv.x;
        t[row][c4 + 1] = kv.y + pv.y;
        t[row][c4 + 2] = kv.z + pv.z;
        t[row][c4 + 3] = kv.w + pv.w;
    }
    __syncthreads();
    {
        __align__(16) __half2 o[4];
#pragma unroll
        for (int j = 0; j < 4; j++)
            o[j] = __floats2half2_rn(t[shb + 2 * j][sn], t[shb + 2 * j + 1][sn]);
        *(uint4*)(g_Kt + obase + (size_t)(n0 + sn) * HDIM + h0 + shb) = *(uint4*)o;
    }
}

// Pre-pass 2: V -> fp16
__global__ __launch_bounds__(256)
void conv_v(const float* __restrict__ V) {
    const size_t i = ((size_t)blockIdx.x * 256 + threadIdx.x) * 8;
    const float4 v0 = *(const float4*)(V + i);
    const float4 v1 = *(const float4*)(V + i + 4);
    __align__(16) __half2 o[4];
    o[0] = __floats2half2_rn(v0.x, v0.y);
    o[1] = __floats2half2_rn(v0.z, v0.w);
    o[2] = __floats2half2_rn(v1.x, v1.y);
    o[3] = __floats2half2_rn(v1.z, v1.w);
    *(uint4*)(g_Vh + i) = *(uint4*)o;
}

// ===========================================================================
// Warp tile (16*MF rows A) x 32 (B rows). Per chunk: 4 ks of
// MF LDSM.x4 (A) + 2 LDSM.x4 (B) + 4*MF HMMA.
// ===========================================================================
template <int MF>
__device__ __forceinline__ void mma_chunk(float acc[MF][4][4], uint32_t stA, uint32_t stB,
                                          int wa, int wb, int lane) {
    const uint32_t aoff = stA + ((uint32_t)(wa + (lane & 15)) * PITCH + ((lane >> 4) * 8)) * 2;
    const uint32_t boff = stB + ((uint32_t)(wb + ((lane & 7) | ((lane & 16) >> 1))) * PITCH
                                 + (((lane >> 3) & 1) * 8)) * 2;
#pragma unroll
    for (int ks = 0; ks < 4; ks++) {
        uint32_t a[MF][4], bb[4][2];
        const uint32_t kb = ks * 32;   // 16 halfs = 32 bytes per ks
#pragma unroll
        for (int mf = 0; mf < MF; mf++)
            LDSM_X4(a[mf][0], a[mf][1], a[mf][2], a[mf][3],
                    aoff + kb + mf * (16 * PITCH * 2));
#pragma unroll
        for (int n2 = 0; n2 < 2; n2++)
            LDSM_X4(bb[2 * n2][0], bb[2 * n2][1], bb[2 * n2 + 1][0], bb[2 * n2 + 1][1],
                    boff + kb + n2 * (16 * PITCH * 2));
#pragma unroll
        for (int mf = 0; mf < MF; mf++)
#pragma unroll
            for (int nf = 0; nf < 4; nf++)
                mma_f16(acc[mf][nf], a[mf], bb[nf]);
    }
}

// ===========================================================================
// GEMM1 (persistent): S[n][m] = sum_h Qt[n][h]*Kt[m][h]. Tile 128(n)x128(m),
// 4096 tiles strided over 296 CTAs; continuous cross-tile mbarrier ring.
// ===========================================================================
__global__ __launch_bounds__(NTHREADS, 2)
void gemm1_k() {
    extern __shared__ __half S[];
    const int tid = threadIdx.x, lane = tid & 31, w = tid >> 5;
    const int gid = lane >> 2, tig = lane & 3;
    const int wn = (w & 1) * 64;    // n offset (A rows)
    const int wm = (w >> 1) * 32;   // m offset (B rows)

    const uint32_t sbase = smem_u32(S);
    const uint32_t mbF = sbase + MBAR_OFF1;
    const uint32_t mbE = mbF + 24;

    if (tid == 0) {
#pragma unroll
        for (int s = 0; s < NSTAGE; s++) {
            MBAR_INIT(mbF + s * 8, NTHREADS);
            MBAR_INIT(mbE + s * 8, NWARPS);
        }
    }
    __syncthreads();

    const int NCPT = HDIM / KC;   // 12
    const int NTILES = 4096;
    const int my_tiles = (NTILES - blockIdx.x + NCTAS - 1) / NCTAS;
    const int total_chunks = my_tiles * NCPT;

    int fstg = 0, fpar = 0;   // fill cursor ring state (tracks sequential g)
    auto fill_g = [&](int g) {
        const int ti = g / NCPT, lc = g - ti * NCPT;
        const int tile = blockIdx.x + ti * NCTAS;
        const int bb = tile >> 8, rem = tile & 255;
        const int m0 = (rem & 15) << 7, n0 = ((rem >> 4) & 15) << 7;
        const __half* Qb = g_Qt + (size_t)bb * NDIM * HDIM + (size_t)n0 * HDIM;
        const __half* Kb = g_Kt + (size_t)bb * NDIM * HDIM + (size_t)m0 * HDIM;
        if (g >= NSTAGE) MBAR_WAIT(mbE + fstg * 8, fpar ^ 1);
        const int hc = lc * KC;
        const uint32_t dA = sbase + fstg * STAGE1 * 2;
        const uint32_t dB = dA + STAGE_A1 * 2;
#pragma unroll
        for (int i = 0; i < 4; i++) {   // A: 128 rows x 8 units
            const int idx = i * NTHREADS + tid, row = idx >> 3, u = idx & 7;
            cpa16(dA + (row * PITCH + u * 8) * 2, Qb + (size_t)row * HDIM + hc + u * 8);
        }
#pragma unroll
        for (int i = 0; i < 4; i++) {   // B: 128 rows x 8 units
            const int idx = i * NTHREADS + tid, row = idx >> 3, u = idx & 7;
            cpa16(dB + (row * PITCH + u * 8) * 2, Kb + (size_t)row * HDIM + hc + u * 8);
        }
        CP_MBAR_ARRIVE(mbF + fstg * 8);
        if (++fstg == NSTAGE) { fstg = 0; fpar ^= 1; }
    };

    fill_g(0); fill_g(1);
    int cstg = 0, cpar = 0, g = 0;
    const float scale = 0.03608439182435161f;   // 1/sqrt(768)
    float* Lred = (float*)(S + NSTAGE * STAGE1);

#pragma unroll 1
    for (int i = 0; i < my_tiles; i++) {
        const int tile = blockIdx.x + i * NCTAS;
        const int bb = tile >> 8, rem = tile & 255;
        const int midx = rem & 15, m0 = midx << 7, n0 = ((rem >> 4) & 15) << 7;

        float acc[4][4][4];
#pragma unroll
        for (int x = 0; x < 4; x++)
#pragma unroll
            for (int y = 0; y < 4; y++)
#pragma unroll
                for (int r = 0; r < 4; r++) acc[x][y][r] = 0.f;

#pragma unroll 1
        for (int c = 0; c < NCPT; c++, g++) {
            MBAR_WAIT(mbF + cstg * 8, cpar);
            const uint32_t stA = sbase + cstg * STAGE1 * 2;
            mma_chunk<4>(acc, stA, stA + STAGE_A1 * 2, wn, wm, lane);
            if (lane == 0) MBAR_ARRIVE(mbE + cstg * 8);
            if (g + 2 < total_chunks) fill_g(g + 2);
            if (++cstg == NSTAGE) { cstg = 0; cpar ^= 1; }
        }
        __syncthreads();

        // Epilogue: round to fp16, store E, rowsum of rounded values.
        __half* Eb = g_Eh + (size_t)bb * NDIM * NDIM;
#pragma unroll
        for (int mf = 0; mf < 4; mf++) {
            float rs0 = 0.f, rs1 = 0.f;
#pragma unroll
            for (int nf = 0; nf < 4; nf++) {
                __half2 h01 = __floats2half2_rn(__expf(acc[mf][nf][0] * scale),
                                                __expf(acc[mf][nf][1] * scale));
                __half2 h23 = __floats2half2_rn(__expf(acc[mf][nf][2] * scale),
                                                __expf(acc[mf][nf][3] * scale));
                float2 f01 = __half22float2(h01);
                float2 f23 = __half22float2(h23);
                rs0 += f01.x + f01.y;
                rs1 += f23.x + f23.y;
                const int row = n0 + wn + mf * 16 + gid;
                const int col = m0 + wm + nf * 8 + tig * 2;
                *(__half2*)(Eb + (size_t)row * NDIM + col)       = h01;
                *(__half2*)(Eb + (size_t)(row + 8) * NDIM + col) = h23;
            }
            rs0 += __shfl_xor_sync(0xffffffffu, rs0, 1);
            rs0 += __shfl_xor_sync(0xffffffffu, rs0, 2);
            rs1 += __shfl_xor_sync(0xffffffffu, rs1, 1);
            rs1 += __shfl_xor_sync(0xffffffffu, rs1, 2);
            if (tig == 0) {
                Lred[(w >> 1) * 128 + wn + mf * 16 + gid]     = rs0;
                Lred[(w >> 1) * 128 + wn + mf * 16 + gid + 8] = rs1;
            }
        }
        __syncthreads();
        if (tid < 128) {
            float s = 0.f;
#pragma unroll
            for (int j = 0; j < 4; j++) s += Lred[j * 128 + tid];
            g_Lpart[((size_t)bb * 16 + midx) * NDIM + n0 + tid] = s;
        }
        __syncthreads();
    }
}

// ===========================================================================
__global__ void rowsum_k() {
    const int t = blockIdx.x * blockDim.x + threadIdx.x;
    const int b = t >> 11, n = t & 2047;
    float s = 0.f;
#pragma unroll
    for (int j = 0; j < 16; j++)
        s += g_Lpart[((size_t)b * 16 + j) * NDIM + n];
    g_L[(size_t)b * NDIM + n] = 1.0f / s;
}

// ===========================================================================
// GEMM2 (persistent): O[h][n] = (sum_m Vh[h][m]*Eh[n][m]) * Linv[n].
// Tile 96(h) x 128(n); 2048 tiles (16n x 8h x 16b) over 296 CTAs.
// 8 warps = 2(h) x 4(n), warp tile 48x32 (MF=3).
// ===========================================================================
__global__ __launch_bounds__(NTHREADS, 2)
void gemm2_k(float* __restrict__ out) {
    extern __shared__ __half S[];
    const int tid = threadIdx.x, lane = tid & 31, w = tid >> 5;
    const int gid = lane >> 2, tig = lane & 3;
    const int wh = (w & 1) * 48;    // h offset (A rows)
    const int wn = (w >> 1) * 32;   // n offset (B rows)

    const uint32_t sbase = smem_u32(S);
    const uint32_t mbF = sbase + MBAR_OFF2;
    const uint32_t mbE = mbF + 24;

    if (tid == 0) {
#pragma unroll
        for (int s = 0; s < NSTAGE; s++) {
            MBAR_INIT(mbF + s * 8, NTHREADS);
            MBAR_INIT(mbE + s * 8, NWARPS);
        }
    }
    __syncthreads();

    const int NCPT = NDIM / KC;   // 32
    const int NTILES = 2048;
    const int my_tiles = (NTILES - blockIdx.x + NCTAS - 1) / NCTAS;
    const int total_chunks = my_tiles * NCPT;

    int fstg = 0, fpar = 0;
    auto fill_g = [&](int g) {
        const int ti = g >> 5, lc = g & 31;
        const int tile = blockIdx.x + ti * NCTAS;
        const int bb = tile >> 7;
        const int n0 = (tile & 15) << 7, h0 = ((tile >> 4) & 7) * 96;
        const __half* Vb = g_Vh + (size_t)bb * HDIM * NDIM + (size_t)h0 * NDIM;
        const __half* Eb = g_Eh + (size_t)bb * NDIM * NDIM + (size_t)n0 * NDIM;
        if (g >= NSTAGE) MBAR_WAIT(mbE + fstg * 8, fpar ^ 1);
        const int mc = lc * KC;
        const uint32_t dA = sbase + fstg * STAGE2 * 2;
        const uint32_t dB = dA + STAGE_A2 * 2;
#pragma unroll
        for (int i = 0; i < 3; i++) {   // A: 96 rows x 8 units = 768 ops
            const int idx = i * NTHREADS + tid, row = idx >> 3, u = idx & 7;
            cpa16(dA + (row * PITCH + u * 8) * 2, Vb + (size_t)row * NDIM + mc + u * 8);
        }
#pragma unroll
        for (int i = 0; i < 4; i++) {   // B: 128 rows x 8 units = 1024 ops
            const int idx = i * NTHREADS + tid, row = idx >> 3, u = idx & 7;
            cpa16(dB + (row * PITCH + u * 8) * 2, Eb + (size_t)row * NDIM + mc + u * 8);
        }
        CP_MBAR_ARRIVE(mbF + fstg * 8);
        if (++fstg == NSTAGE) { fstg = 0; fpar ^= 1; }
    };

    fill_g(0); fill_g(1);
    int cstg = 0, cpar = 0, g = 0;

#pragma unroll 1
    for (int i = 0; i < my_tiles; i++) {
        const int tile = blockIdx.x + i * NCTAS;
        const int bb = tile >> 7;
        const int n0 = (tile & 15) << 7, h0 = ((tile >> 4) & 7) * 96;

        float acc[3][4][4];
#pragma unroll
        for (int x = 0; x < 3; x++)
#pragma unroll
            for (int y = 0; y < 4; y++)
#pragma unroll
                for (int r = 0; r < 4; r++) acc[x][y][r] = 0.f;

#pragma unroll 1
        for (int c = 0; c < NCPT; c++, g++) {
            MBAR_WAIT(mbF + cstg * 8, cpar);
            const uint32_t stA = sbase + cstg * STAGE2 * 2;
            mma_chunk<3>(acc, stA, stA + STAGE_A2 * 2, wh, wn, lane);
            if (lane == 0) MBAR_ARRIVE(mbE + cstg * 8);
            if (g + 2 < total_chunks) fill_g(g + 2);
            if (++cstg == NSTAGE) { cstg = 0; cpar ^= 1; }
        }

        // Epilogue: multiply by 1/L[n], store fp32
        const float* Li = g_L + (size_t)bb * NDIM;
#pragma unroll
        for (int nf = 0; nf < 4; nf++) {
            const int col = n0 + wn + nf * 8 + tig * 2;
            const float iv0 = Li[col], iv1 = Li[col + 1];
#pragma unroll
            for (int mf = 0; mf < 3; mf++) {
                const int row = h0 + wh + mf * 16 + gid;
                *(float2*)(out + (size_t)(bb * HDIM + row) * NDIM + col) =
                    make_float2(acc[mf][nf][0] * iv0, acc[mf][nf][1] * iv1);
                *(float2*)(out + (size_t)(bb * HDIM + row + 8) * NDIM + col) =
                    make_float2(acc[mf][nf][2] * iv0, acc[mf][nf][3] * iv1);
            }
        }
    }
}

// ===========================================================================
extern "C" void kernel_launch(void* const* d_in, const int* in_sizes, int n_in,
                              void* d_out, int out_size) {
    const float* q  = (const float*)d_in[0];
    const float* k  = (const float*)d_in[1];
    const float* v  = (const float*)d_in[2];
    const float* pe = (const float*)d_in[3];
    float* out = (float*)d_out;

    cudaFuncSetAttribute(gemm1_k, cudaFuncAttributeMaxDynamicSharedMemorySize, SMEM1);
    cudaFuncSetAttribute(gemm2_k, cudaFuncAttributeMaxDynamicSharedMemorySize, SMEM2);

    prep_qk<<<dim3(NDIM / 64, HDIM / 64, BATCH), 512>>>(q, k, pe);
    conv_v<<<(BATCH * HDIM * NDIM) / 2048, 256>>>(v);
    gemm1_k<<<NCTAS, NTHREADS, SMEM1>>>();
    rowsum_k<<<(BATCH * NDIM) / 256, 256>>>();
    gemm2_k<<<NCTAS, NTHREADS, SMEM2>>>(out);
}